// round 8
// baseline (speedup 1.0000x reference)
#include <cuda_runtime.h>

// LSTM B=4096, T=999, I=1, H=51, O=1, future=0.
//
// R5 pairing + single-wave scheduling:
//   CTA = 16 batches, 128 threads, grid 256 -> 2 CTAs/SM, ONE wave.
//   tid = 2*j + p: p0 owns gate rows i(j), g(2H+j); p1 owns f(H+j), o(3H+j)
//   and the cell state for all 16 batches. Weights: 52 u64 registers
//   (horizontal f32x2 pairs). Per step: 16 batches processed as 8 pairs
//   (4 live accumulators each) -> 832 FFMA2 vs 208 uniform LDS.128.
//   Gate exchange: ONE shfl_xor(1) u64 per batch pair. One barrier/step.
//   h SMEM is batch-major [b][kp] so publishes are conflict-free.
//   x staged in double-buffered 128-step tiles; FC on pad lanes, deferred.

#define HID    51
#define KP     26
#define SEQLEN 999
#define BT     16
#define NTHR   128
#define BATCH  4096

typedef unsigned long long u64;

__device__ __forceinline__ u64 pk2(float lo, float hi) {
    u64 r;
    asm("mov.b64 %0, {%1, %2};"
        : "=l"(r) : "r"(__float_as_uint(lo)), "r"(__float_as_uint(hi)));
    return r;
}
__device__ __forceinline__ void upk2(u64 v, float& lo, float& hi) {
    unsigned a, b;
    asm("mov.b64 {%0, %1}, %2;" : "=r"(a), "=r"(b) : "l"(v));
    lo = __uint_as_float(a); hi = __uint_as_float(b);
}
__device__ __forceinline__ u64 ffma2(u64 a, u64 b, u64 c) {
    u64 d; asm("fma.rn.f32x2 %0, %1, %2, %3;" : "=l"(d) : "l"(a), "l"(b), "l"(c));
    return d;
}
__device__ __forceinline__ u64 fmul2(u64 a, u64 b) {
    u64 d; asm("mul.rn.f32x2 %0, %1, %2;" : "=l"(d) : "l"(a), "l"(b));
    return d;
}
__device__ __forceinline__ float fast_sig_scaled(float a, float kl2) {
    // sigmoid(ks*a), kl2 = -ks*log2(e)
    float e; asm("ex2.approx.f32 %0, %1;" : "=f"(e) : "f"(a * kl2));
    float r; asm("rcp.approx.f32 %0, %1;" : "=f"(r) : "f"(e + 1.0f));
    return r;
}
__device__ __forceinline__ float fast_tanh(float x) {
    float e; asm("ex2.approx.f32 %0, %1;"
                 : "=f"(e) : "f"(x * -2.8853900817779268f));
    float r; asm("rcp.approx.f32 %0, %1;" : "=f"(r) : "f"(e + 1.0f));
    return fmaf(2.0f, r, -1.0f);
}

__global__ __launch_bounds__(NTHR, 2)
void lstm7_kernel(const float* __restrict__ input,   // (B, T, 1)
                  const float* __restrict__ W_ih,    // (4H, 1)
                  const float* __restrict__ W_hh,    // (4H, H)
                  const float* __restrict__ b_ih,    // (4H)
                  const float* __restrict__ b_hh,    // (4H)
                  const float* __restrict__ W_fc,    // (1, H)
                  const float* __restrict__ b_fc,    // (1)
                  float* __restrict__ out)           // (B, T, 1)
{
    __shared__ __align__(16) float xt[2][128][BT];    // 16 KB, x tiles
    __shared__ __align__(16) u64   hsh[2][BT][KP];    // 6.5 KB, batch-major h
    __shared__ __align__(16) u64   wfc2[KP];

    const int tid = threadIdx.x;
    const int b0  = blockIdx.x * BT;

    // ---- one-time init ----
    for (int idx = tid; idx < 2 * BT * KP; idx += NTHR)
        ((u64*)hsh)[idx] = 0ull;                      // h0 = 0 (+ pad lanes)
    if (tid < KP)
        wfc2[tid] = pk2(W_fc[2 * tid],
                        (2 * tid + 1 < HID) ? W_fc[2 * tid + 1] : 0.0f);
    {   // preload x tile 0 (t = 0..127)
        #pragma unroll
        for (int b = 0; b < BT; b++)
            xt[0][tid][b] = input[(b0 + b) * SEQLEN + tid];
    }

    const int j = tid >> 1;           // unit 0..50 (active)
    const int p = tid & 1;            // 0 = (i,g), 1 = (f,o)+cell
    const bool active = (tid < 2 * HID);              // < 102
    const bool fcRole = (tid >= 104 && tid < 104 + BT);
    const int  fb     = tid - 104;
    const unsigned wmask = (tid >= 96) ? 0x3Fu : 0xFFFFFFFFu;

    const int row1 = p * HID + j;         // i or f
    const int row2 = (2 + p) * HID + j;   // g or o

    u64 w1[KP], w2[KP];
    float bias1 = 0.f, bias2 = 0.f, wih1 = 0.f, wih2 = 0.f;
    if (active) {
        #pragma unroll
        for (int q = 0; q < KP; q++) {
            int k0 = 2 * q, k1 = 2 * q + 1;
            float a0 = W_hh[row1 * HID + k0];
            float a1 = (k1 < HID) ? W_hh[row1 * HID + k1] : 0.0f;
            float c0 = W_hh[row2 * HID + k0];
            float c1 = (k1 < HID) ? W_hh[row2 * HID + k1] : 0.0f;
            w1[q] = pk2(a0, a1);
            w2[q] = pk2(c0, c1);
        }
        bias1 = b_ih[row1] + b_hh[row1];
        bias2 = b_ih[row2] + b_hh[row2];
        wih1  = W_ih[row1];
        wih2  = W_ih[row2];
    } else {
        #pragma unroll
        for (int q = 0; q < KP; q++) { w1[q] = 0ull; w2[q] = 0ull; }
    }
    const float bfc = b_fc[0];

    // row1 (i|f): sigmoid. row2: tanh for p0 (g), sigmoid for p1 (o).
    const float KL2   = -1.4426950408889634f;
    const float kl2_2 = (p == 0) ? -2.8853900817779268f : -1.4426950408889634f;
    const float mm2   = (p == 0) ? 2.0f : 1.0f;
    const float ba2   = (p == 0) ? -1.0f : 0.0f;

    u64 cst[BT / 2];                      // cell state pairs (p1 lanes)
    #pragma unroll
    for (int q = 0; q < BT / 2; q++) cst[q] = 0ull;

    __syncthreads();

    #pragma unroll 1
    for (int t = 0; t < SEQLEN; t++) {
        const u64* __restrict__ hb = &hsh[t & 1][0][0];

        // ---- prefetch next x tile (every 128th step; consumed 128 later) --
        if ((t & 127) == 0) {
            const int t0 = t + 128;
            if (t0 < SEQLEN) {
                const int buf = (t0 >> 7) & 1;
                const int tt  = t0 + tid;
                if (tt < SEQLEN) {
                    #pragma unroll
                    for (int b = 0; b < BT; b++)
                        xt[buf][tid][b] = input[(b0 + b) * SEQLEN + tt];
                }
            }
        }

        // ---- deferred FC for step t-1 (pad lanes; stable buffer) ----
        if (fcRole && t > 0) {
            const u64* __restrict__ hv = hb + fb * KP;
            u64 s0 = 0ull, s1 = 0ull;
            #pragma unroll
            for (int q = 0; q < KP; q += 2) {
                s0 = ffma2(hv[q],     wfc2[q],     s0);
                s1 = ffma2(hv[q + 1], wfc2[q + 1], s1);
            }
            float aa, ab, ac, ad;
            upk2(s0, aa, ab); upk2(s1, ac, ad);
            out[(b0 + fb) * SEQLEN + (t - 1)] = (aa + ab) + (ac + ad) + bfc;
        }

        if (active) {
            const float* __restrict__ xrow = xt[(t >> 7) & 1][t & 127];
            u64* __restrict__ hw = &hsh[(t + 1) & 1][0][0];
            u64 a1p[BT / 2], a2p[BT / 2];

            // ---- phase 1: dots + activations, batch pairs ----
            #pragma unroll
            for (int bb = 0; bb < BT / 2; bb++) {
                const u64* __restrict__ h0 = hb + (2 * bb) * KP;
                const u64* __restrict__ h1 = hb + (2 * bb + 1) * KP;
                u64 A = 0ull, B = 0ull, C = 0ull, D = 0ull;
                #pragma unroll
                for (int q = 0; q < KP; q += 2) {
                    ulonglong2 u = *(const ulonglong2*)(h0 + q);
                    ulonglong2 v = *(const ulonglong2*)(h1 + q);
                    A = ffma2(w1[q], u.x, A); A = ffma2(w1[q + 1], u.y, A);
                    B = ffma2(w1[q], v.x, B); B = ffma2(w1[q + 1], v.y, B);
                    C = ffma2(w2[q], u.x, C); C = ffma2(w2[q + 1], u.y, C);
                    D = ffma2(w2[q], v.x, D); D = ffma2(w2[q + 1], v.y, D);
                }
                const float2 xv = *(const float2*)(xrow + 2 * bb);
                float lo, hi;
                upk2(A, lo, hi); const float g10 = (lo + hi) + fmaf(xv.x, wih1, bias1);
                upk2(B, lo, hi); const float g11 = (lo + hi) + fmaf(xv.y, wih1, bias1);
                upk2(C, lo, hi); const float g20 = (lo + hi) + fmaf(xv.x, wih2, bias2);
                upk2(D, lo, hi); const float g21 = (lo + hi) + fmaf(xv.y, wih2, bias2);
                const float s10 = fast_sig_scaled(g10, KL2);
                const float s11 = fast_sig_scaled(g11, KL2);
                const float s20 = fmaf(mm2, fast_sig_scaled(g20, kl2_2), ba2);
                const float s21 = fmaf(mm2, fast_sig_scaled(g21, kl2_2), ba2);
                a1p[bb] = pk2(s10, s11);
                a2p[bb] = pk2(s20, s21);
            }

            // ---- exchange + cell/h update ----
            #pragma unroll
            for (int bb = 0; bb < BT / 2; bb++) {
                u64 pr = fmul2(a1p[bb], a2p[bb]);        // p0: sig(i)*tanh(g)
                u64 rr = __shfl_xor_sync(wmask, pr, 1, 32);
                if (p == 1) {
                    // c = sig(f)*c + sig(i)*tanh(g); h = sig(o)*tanh(c)
                    cst[bb] = ffma2(a1p[bb], cst[bb], rr);
                    float c0, c1; upk2(cst[bb], c0, c1);
                    float o0, o1; upk2(a2p[bb], o0, o1);
                    const float h0v = o0 * fast_tanh(c0);
                    const float h1v = o1 * fast_tanh(c1);
                    float* d0 = (float*)(hw + (2 * bb) * KP + (j >> 1)) + (j & 1);
                    float* d1 = (float*)(hw + (2 * bb + 1) * KP + (j >> 1)) + (j & 1);
                    *d0 = h0v;
                    *d1 = h1v;
                }
            }
        }
        __syncthreads();
    }

    // final FC for t = SEQLEN-1
    if (fcRole) {
        const u64* __restrict__ hv = &hsh[SEQLEN & 1][fb][0];
        u64 s0 = 0ull, s1 = 0ull;
        #pragma unroll
        for (int q = 0; q < KP; q += 2) {
            s0 = ffma2(hv[q],     wfc2[q],     s0);
            s1 = ffma2(hv[q + 1], wfc2[q + 1], s1);
        }
        float aa, ab, ac, ad;
        upk2(s0, aa, ab); upk2(s1, ac, ad);
        out[(b0 + fb) * SEQLEN + (SEQLEN - 1)] = (aa + ab) + (ac + ad) + bfc;
    }
}

extern "C" void kernel_launch(void* const* d_in, const int* in_sizes, int n_in,
                              void* d_out, int out_size) {
    const float* input = (const float*)d_in[0];
    const float* W_ih  = (const float*)d_in[1];
    const float* W_hh  = (const float*)d_in[2];
    const float* b_ih  = (const float*)d_in[3];
    const float* b_hh  = (const float*)d_in[4];
    const float* W_fc  = (const float*)d_in[5];
    const float* b_fc  = (const float*)d_in[6];
    // d_in[7] = future (0) — ignored.
    float* out = (float*)d_out;

    lstm7_kernel<<<BATCH / BT, NTHR>>>(input, W_ih, W_hh, b_ih, b_hh,
                                       W_fc, b_fc, out);
}

// round 9
// speedup vs baseline: 1.2089x; 1.2089x over previous
#include <cuda_runtime.h>

// LSTM B=4096, T=999, I=1, H=51, O=1, future=0.
//
// R5 gate-pairing, rescheduled:
//   CTA = 8 batches, 128 threads, grid 512 -> 2 CTAs/SM, 1.73 waves
//   (vs R5's 2.31). tid = 2j+p: p0 owns rows i(j), g(2H+j); p1 owns f(H+j),
//   o(3H+j) + cell state. 52 u64 weight regs (horizontal f32x2 pairs).
//   8 batches processed in 2 chunks of 4 (8 live accums/chunk) to keep
//   regs ~190 (R7 died at 250). h SMEM batch-major [b][kp]: conflict-free
//   publishes, uniform broadcast reads, contiguous FC reads.
//   Activations via tanh.approx.f32 (1 MUFU/act, vs ex2+rcp = 2).
//   One shfl_xor(1) per batch-pair, ONE __syncthreads per step.
//   FC on 8 idle lanes of warp 3 (tid 104..111), deferred one step.

#define HID    51
#define KP     26
#define SEQLEN 999
#define BT     8
#define NTHR   128
#define BATCH  4096

typedef unsigned long long u64;

__device__ __forceinline__ u64 pk2(float lo, float hi) {
    u64 r;
    asm("mov.b64 %0, {%1, %2};"
        : "=l"(r) : "r"(__float_as_uint(lo)), "r"(__float_as_uint(hi)));
    return r;
}
__device__ __forceinline__ void upk2(u64 v, float& lo, float& hi) {
    unsigned a, b;
    asm("mov.b64 {%0, %1}, %2;" : "=r"(a), "=r"(b) : "l"(v));
    lo = __uint_as_float(a); hi = __uint_as_float(b);
}
__device__ __forceinline__ u64 ffma2(u64 a, u64 b, u64 c) {
    u64 d; asm("fma.rn.f32x2 %0, %1, %2, %3;" : "=l"(d) : "l"(a), "l"(b), "l"(c));
    return d;
}
__device__ __forceinline__ u64 fmul2(u64 a, u64 b) {
    u64 d; asm("mul.rn.f32x2 %0, %1, %2;" : "=l"(d) : "l"(a), "l"(b));
    return d;
}
__device__ __forceinline__ float tanha(float x) {
    float r; asm("tanh.approx.f32 %0, %1;" : "=f"(r) : "f"(x));
    return r;
}

__global__ __launch_bounds__(NTHR, 2)
void lstm8_kernel(const float* __restrict__ input,   // (B, T, 1)
                  const float* __restrict__ W_ih,    // (4H, 1)
                  const float* __restrict__ W_hh,    // (4H, H)
                  const float* __restrict__ b_ih,    // (4H)
                  const float* __restrict__ b_hh,    // (4H)
                  const float* __restrict__ W_fc,    // (1, H)
                  const float* __restrict__ b_fc,    // (1)
                  float* __restrict__ out)           // (B, T, 1)
{
    __shared__ __align__(16) float xsh[SEQLEN][BT];   // 31.2 KB
    __shared__ __align__(16) u64   hsh[2][BT][KP];    // 3.25 KB, batch-major
    __shared__ __align__(16) u64   wfc2[KP];

    const int tid = threadIdx.x;
    const int b0  = blockIdx.x * BT;

    // ---- one-time init ----
    #pragma unroll
    for (int b = 0; b < BT; b++)
        for (int idx = tid; idx < SEQLEN; idx += NTHR)
            xsh[idx][b] = input[(b0 + b) * SEQLEN + idx];
    for (int idx = tid; idx < 2 * BT * KP; idx += NTHR)
        ((u64*)hsh)[idx] = 0ull;                      // h0 = 0 (+ pad lanes)
    if (tid < KP)
        wfc2[tid] = pk2(W_fc[2 * tid],
                        (2 * tid + 1 < HID) ? W_fc[2 * tid + 1] : 0.0f);

    const int j = tid >> 1;           // unit 0..50 (active)
    const int p = tid & 1;            // 0 = (i,g), 1 = (f,o)+cell
    const bool active = (tid < 2 * HID);              // < 102
    const bool fcRole = (tid >= 104 && tid < 104 + BT);
    const int  fb     = tid - 104;
    const unsigned wmask = (tid >= 96) ? 0x3Fu : 0xFFFFFFFFu;

    const int row1 = p * HID + j;         // i or f
    const int row2 = (2 + p) * HID + j;   // g or o

    u64 w1[KP], w2[KP];
    float bias1 = 0.f, bias2 = 0.f, wih1 = 0.f, wih2 = 0.f;
    if (active) {
        #pragma unroll
        for (int q = 0; q < KP; q++) {
            int k0 = 2 * q, k1 = 2 * q + 1;
            float a0 = W_hh[row1 * HID + k0];
            float a1 = (k1 < HID) ? W_hh[row1 * HID + k1] : 0.0f;
            float c0 = W_hh[row2 * HID + k0];
            float c1 = (k1 < HID) ? W_hh[row2 * HID + k1] : 0.0f;
            w1[q] = pk2(a0, a1);
            w2[q] = pk2(c0, c1);
        }
        bias1 = b_ih[row1] + b_hh[row1];
        bias2 = b_ih[row2] + b_hh[row2];
        wih1  = W_ih[row1];
        wih2  = W_ih[row2];
    } else {
        #pragma unroll
        for (int q = 0; q < KP; q++) { w1[q] = 0ull; w2[q] = 0ull; }
    }
    const float bfc = b_fc[0];

    // act = m2 * tanh(sc2 * a) + a2  (row1 always sigmoid; row2: g->tanh,
    // o->sigmoid).  sigmoid(x) = 0.5*tanh(0.5x) + 0.5.
    const float sc2 = (p == 0) ? 1.0f : 0.5f;
    const float m2  = (p == 0) ? 1.0f : 0.5f;
    const float a2c = (p == 0) ? 0.0f : 0.5f;

    u64 cst[BT / 2];                      // cell pairs (p1 lanes)
    #pragma unroll
    for (int q = 0; q < BT / 2; q++) cst[q] = 0ull;

    __syncthreads();

    #pragma unroll 1
    for (int t = 0; t < SEQLEN; t++) {
        const u64* __restrict__ hb = &hsh[t & 1][0][0];
        u64* __restrict__ hw = &hsh[(t + 1) & 1][0][0];

        // ---- deferred FC for step t-1 (idle lanes; stable buffer) ----
        if (fcRole && t > 0) {
            const u64* __restrict__ hv = hb + fb * KP;
            u64 s0 = 0ull, s1 = 0ull;
            #pragma unroll
            for (int q = 0; q < KP; q += 2) {
                s0 = ffma2(hv[q],     wfc2[q],     s0);
                s1 = ffma2(hv[q + 1], wfc2[q + 1], s1);
            }
            float aa, ab, ac, ad;
            upk2(s0, aa, ab); upk2(s1, ac, ad);
            out[(b0 + fb) * SEQLEN + (t - 1)] = (aa + ab) + (ac + ad) + bfc;
        }

        if (active) {
            #pragma unroll
            for (int ch = 0; ch < 2; ch++) {
                const int cb = ch * 4;
                const u64* __restrict__ h0 = hb + (cb + 0) * KP;
                const u64* __restrict__ h1 = hb + (cb + 1) * KP;
                const u64* __restrict__ h2 = hb + (cb + 2) * KP;
                const u64* __restrict__ h3 = hb + (cb + 3) * KP;

                u64 A0 = 0ull, A1 = 0ull, A2 = 0ull, A3 = 0ull;   // row1
                u64 C0 = 0ull, C1 = 0ull, C2 = 0ull, C3 = 0ull;   // row2
                #pragma unroll
                for (int q = 0; q < KP; q += 2) {
                    ulonglong2 u0 = *(const ulonglong2*)(h0 + q);
                    ulonglong2 u1 = *(const ulonglong2*)(h1 + q);
                    ulonglong2 u2 = *(const ulonglong2*)(h2 + q);
                    ulonglong2 u3 = *(const ulonglong2*)(h3 + q);
                    A0 = ffma2(w1[q], u0.x, A0); A0 = ffma2(w1[q+1], u0.y, A0);
                    A1 = ffma2(w1[q], u1.x, A1); A1 = ffma2(w1[q+1], u1.y, A1);
                    A2 = ffma2(w1[q], u2.x, A2); A2 = ffma2(w1[q+1], u2.y, A2);
                    A3 = ffma2(w1[q], u3.x, A3); A3 = ffma2(w1[q+1], u3.y, A3);
                    C0 = ffma2(w2[q], u0.x, C0); C0 = ffma2(w2[q+1], u0.y, C0);
                    C1 = ffma2(w2[q], u1.x, C1); C1 = ffma2(w2[q+1], u1.y, C1);
                    C2 = ffma2(w2[q], u2.x, C2); C2 = ffma2(w2[q+1], u2.y, C2);
                    C3 = ffma2(w2[q], u3.x, C3); C3 = ffma2(w2[q+1], u3.y, C3);
                }
                const float4 xv = *(const float4*)&xsh[t][cb];
                float lo, hi;
                upk2(A0, lo, hi); const float g10 = (lo + hi) + fmaf(xv.x, wih1, bias1);
                upk2(A1, lo, hi); const float g11 = (lo + hi) + fmaf(xv.y, wih1, bias1);
                upk2(A2, lo, hi); const float g12 = (lo + hi) + fmaf(xv.z, wih1, bias1);
                upk2(A3, lo, hi); const float g13 = (lo + hi) + fmaf(xv.w, wih1, bias1);
                upk2(C0, lo, hi); const float g20 = (lo + hi) + fmaf(xv.x, wih2, bias2);
                upk2(C1, lo, hi); const float g21 = (lo + hi) + fmaf(xv.y, wih2, bias2);
                upk2(C2, lo, hi); const float g22 = (lo + hi) + fmaf(xv.z, wih2, bias2);
                upk2(C3, lo, hi); const float g23 = (lo + hi) + fmaf(xv.w, wih2, bias2);

                // activations (sigmoid via tanh identity; g row raw tanh)
                const float s10 = fmaf(0.5f, tanha(0.5f * g10), 0.5f);
                const float s11 = fmaf(0.5f, tanha(0.5f * g11), 0.5f);
                const float s12 = fmaf(0.5f, tanha(0.5f * g12), 0.5f);
                const float s13 = fmaf(0.5f, tanha(0.5f * g13), 0.5f);
                const float s20 = fmaf(m2, tanha(sc2 * g20), a2c);
                const float s21 = fmaf(m2, tanha(sc2 * g21), a2c);
                const float s22 = fmaf(m2, tanha(sc2 * g22), a2c);
                const float s23 = fmaf(m2, tanha(sc2 * g23), a2c);

                u64 a1p0 = pk2(s10, s11), a1p1 = pk2(s12, s13);
                u64 a2p0 = pk2(s20, s21), a2p1 = pk2(s22, s23);

                // p0: sig(i)*tanh(g) -> partner
                u64 pr0 = fmul2(a1p0, a2p0);
                u64 pr1 = fmul2(a1p1, a2p1);
                u64 rr0 = __shfl_xor_sync(wmask, pr0, 1, 32);
                u64 rr1 = __shfl_xor_sync(wmask, pr1, 1, 32);

                if (p == 1) {
                    // c = sig(f)*c + sig(i)*tanh(g); h = sig(o)*tanh(c)
                    cst[ch * 2]     = ffma2(a1p0, cst[ch * 2],     rr0);
                    cst[ch * 2 + 1] = ffma2(a1p1, cst[ch * 2 + 1], rr1);
                    float c0, c1, c2, c3;
                    upk2(cst[ch * 2],     c0, c1);
                    upk2(cst[ch * 2 + 1], c2, c3);
                    const float h0v = s20 * tanha(c0);
                    const float h1v = s21 * tanha(c1);
                    const float h2v = s22 * tanha(c2);
                    const float h3v = s23 * tanha(c3);
                    const int jh = j >> 1, jl = j & 1;
                    ((float*)(hw + (cb + 0) * KP + jh))[jl] = h0v;
                    ((float*)(hw + (cb + 1) * KP + jh))[jl] = h1v;
                    ((float*)(hw + (cb + 2) * KP + jh))[jl] = h2v;
                    ((float*)(hw + (cb + 3) * KP + jh))[jl] = h3v;
                }
            }
        }
        __syncthreads();
    }

    // final FC for t = SEQLEN-1
    if (fcRole) {
        const u64* __restrict__ hv = &hsh[SEQLEN & 1][fb][0];
        u64 s0 = 0ull, s1 = 0ull;
        #pragma unroll
        for (int q = 0; q < KP; q += 2) {
            s0 = ffma2(hv[q],     wfc2[q],     s0);
            s1 = ffma2(hv[q + 1], wfc2[q + 1], s1);
        }
        float aa, ab, ac, ad;
        upk2(s0, aa, ab); upk2(s1, ac, ad);
        out[(b0 + fb) * SEQLEN + (SEQLEN - 1)] = (aa + ab) + (ac + ad) + bfc;
    }
}

extern "C" void kernel_launch(void* const* d_in, const int* in_sizes, int n_in,
                              void* d_out, int out_size) {
    const float* input = (const float*)d_in[0];
    const float* W_ih  = (const float*)d_in[1];
    const float* W_hh  = (const float*)d_in[2];
    const float* b_ih  = (const float*)d_in[3];
    const float* b_hh  = (const float*)d_in[4];
    const float* W_fc  = (const float*)d_in[5];
    const float* b_fc  = (const float*)d_in[6];
    // d_in[7] = future (0) — ignored.
    float* out = (float*)d_out;

    lstm8_kernel<<<BATCH / BT, NTHR>>>(input, W_ih, W_hh, b_ih, b_hh,
                                       W_fc, b_fc, out);
}

// round 10
// speedup vs baseline: 1.3662x; 1.1301x over previous
#include <cuda_runtime.h>

// LSTM B=4096, T=999, I=1, H=51, O=1, future=0.
//
// R8 kernel re-scheduled for 3 CTAs/SM (the calibrated-model optimum):
//   step_cyc/SMSP = W*BT*104 + 4300/W ; total = waves * 999 * step.
//   BT=8, C=3: waves = 512/444 = 1.15, step = 2496+1433 -> ~2.26 ms pred.
// Deltas vs R8 (which measured 3.32 ms at C=2, regs=232):
//   * __launch_bounds__(128, 3): hard 170-reg cap -> 3 CTAs/SM.
//   * memory clobber between the two 4-batch chunks: stops ptxas from
//     hoisting chunk-1 LDS into chunk 0 (the source of R8's 232 regs).
// Everything else identical to the passing R8 (rel_err 1.3e-6).

#define HID    51
#define KP     26
#define SEQLEN 999
#define BT     8
#define NTHR   128
#define BATCH  4096

typedef unsigned long long u64;

__device__ __forceinline__ u64 pk2(float lo, float hi) {
    u64 r;
    asm("mov.b64 %0, {%1, %2};"
        : "=l"(r) : "r"(__float_as_uint(lo)), "r"(__float_as_uint(hi)));
    return r;
}
__device__ __forceinline__ void upk2(u64 v, float& lo, float& hi) {
    unsigned a, b;
    asm("mov.b64 {%0, %1}, %2;" : "=r"(a), "=r"(b) : "l"(v));
    lo = __uint_as_float(a); hi = __uint_as_float(b);
}
__device__ __forceinline__ u64 ffma2(u64 a, u64 b, u64 c) {
    u64 d; asm("fma.rn.f32x2 %0, %1, %2, %3;" : "=l"(d) : "l"(a), "l"(b), "l"(c));
    return d;
}
__device__ __forceinline__ u64 fmul2(u64 a, u64 b) {
    u64 d; asm("mul.rn.f32x2 %0, %1, %2;" : "=l"(d) : "l"(a), "l"(b));
    return d;
}
__device__ __forceinline__ float tanha(float x) {
    float r; asm("tanh.approx.f32 %0, %1;" : "=f"(r) : "f"(x));
    return r;
}

__global__ __launch_bounds__(NTHR, 3)
void lstm9_kernel(const float* __restrict__ input,   // (B, T, 1)
                  const float* __restrict__ W_ih,    // (4H, 1)
                  const float* __restrict__ W_hh,    // (4H, H)
                  const float* __restrict__ b_ih,    // (4H)
                  const float* __restrict__ b_hh,    // (4H)
                  const float* __restrict__ W_fc,    // (1, H)
                  const float* __restrict__ b_fc,    // (1)
                  float* __restrict__ out)           // (B, T, 1)
{
    __shared__ __align__(16) float xsh[SEQLEN][BT];   // 31.2 KB
    __shared__ __align__(16) u64   hsh[2][BT][KP];    // 3.25 KB, batch-major
    __shared__ __align__(16) u64   wfc2[KP];

    const int tid = threadIdx.x;
    const int b0  = blockIdx.x * BT;

    // ---- one-time init ----
    #pragma unroll
    for (int b = 0; b < BT; b++)
        for (int idx = tid; idx < SEQLEN; idx += NTHR)
            xsh[idx][b] = input[(b0 + b) * SEQLEN + idx];
    for (int idx = tid; idx < 2 * BT * KP; idx += NTHR)
        ((u64*)hsh)[idx] = 0ull;                      // h0 = 0 (+ pad lanes)
    if (tid < KP)
        wfc2[tid] = pk2(W_fc[2 * tid],
                        (2 * tid + 1 < HID) ? W_fc[2 * tid + 1] : 0.0f);

    const int j = tid >> 1;           // unit 0..50 (active)
    const int p = tid & 1;            // 0 = (i,g), 1 = (f,o)+cell
    const bool active = (tid < 2 * HID);              // < 102
    const bool fcRole = (tid >= 104 && tid < 104 + BT);
    const int  fb     = tid - 104;
    const unsigned wmask = (tid >= 96) ? 0x3Fu : 0xFFFFFFFFu;

    const int row1 = p * HID + j;         // i or f
    const int row2 = (2 + p) * HID + j;   // g or o

    u64 w1[KP], w2[KP];
    float bias1 = 0.f, bias2 = 0.f, wih1 = 0.f, wih2 = 0.f;
    if (active) {
        #pragma unroll
        for (int q = 0; q < KP; q++) {
            int k0 = 2 * q, k1 = 2 * q + 1;
            float a0 = W_hh[row1 * HID + k0];
            float a1 = (k1 < HID) ? W_hh[row1 * HID + k1] : 0.0f;
            float c0 = W_hh[row2 * HID + k0];
            float c1 = (k1 < HID) ? W_hh[row2 * HID + k1] : 0.0f;
            w1[q] = pk2(a0, a1);
            w2[q] = pk2(c0, c1);
        }
        bias1 = b_ih[row1] + b_hh[row1];
        bias2 = b_ih[row2] + b_hh[row2];
        wih1  = W_ih[row1];
        wih2  = W_ih[row2];
    } else {
        #pragma unroll
        for (int q = 0; q < KP; q++) { w1[q] = 0ull; w2[q] = 0ull; }
    }
    const float bfc = b_fc[0];

    // act = m2 * tanh(sc2 * a) + a2  (row1 always sigmoid; row2: g->tanh,
    // o->sigmoid).  sigmoid(x) = 0.5*tanh(0.5x) + 0.5.
    const float sc2 = (p == 0) ? 1.0f : 0.5f;
    const float m2  = (p == 0) ? 1.0f : 0.5f;
    const float a2c = (p == 0) ? 0.0f : 0.5f;

    u64 cst[BT / 2];                      // cell pairs (p1 lanes)
    #pragma unroll
    for (int q = 0; q < BT / 2; q++) cst[q] = 0ull;

    __syncthreads();

    #pragma unroll 1
    for (int t = 0; t < SEQLEN; t++) {
        const u64* __restrict__ hb = &hsh[t & 1][0][0];
        u64* __restrict__ hw = &hsh[(t + 1) & 1][0][0];

        // ---- deferred FC for step t-1 (idle lanes; stable buffer) ----
        if (fcRole && t > 0) {
            const u64* __restrict__ hv = hb + fb * KP;
            u64 s0 = 0ull, s1 = 0ull;
            #pragma unroll
            for (int q = 0; q < KP; q += 2) {
                s0 = ffma2(hv[q],     wfc2[q],     s0);
                s1 = ffma2(hv[q + 1], wfc2[q + 1], s1);
            }
            float aa, ab, ac, ad;
            upk2(s0, aa, ab); upk2(s1, ac, ad);
            out[(b0 + fb) * SEQLEN + (t - 1)] = (aa + ab) + (ac + ad) + bfc;
        }

        if (active) {
            #pragma unroll
            for (int ch = 0; ch < 2; ch++) {
                // fence compile-time code motion between chunks: keeps
                // chunk-1 LDS from being hoisted into chunk 0 (reg blowup)
                if (ch == 1) asm volatile("" ::: "memory");

                const int cb = ch * 4;
                const u64* __restrict__ h0 = hb + (cb + 0) * KP;
                const u64* __restrict__ h1 = hb + (cb + 1) * KP;
                const u64* __restrict__ h2 = hb + (cb + 2) * KP;
                const u64* __restrict__ h3 = hb + (cb + 3) * KP;

                u64 A0 = 0ull, A1 = 0ull, A2 = 0ull, A3 = 0ull;   // row1
                u64 C0 = 0ull, C1 = 0ull, C2 = 0ull, C3 = 0ull;   // row2
                #pragma unroll
                for (int q = 0; q < KP; q += 2) {
                    ulonglong2 u0 = *(const ulonglong2*)(h0 + q);
                    ulonglong2 u1 = *(const ulonglong2*)(h1 + q);
                    ulonglong2 u2 = *(const ulonglong2*)(h2 + q);
                    ulonglong2 u3 = *(const ulonglong2*)(h3 + q);
                    A0 = ffma2(w1[q], u0.x, A0); A0 = ffma2(w1[q+1], u0.y, A0);
                    A1 = ffma2(w1[q], u1.x, A1); A1 = ffma2(w1[q+1], u1.y, A1);
                    A2 = ffma2(w1[q], u2.x, A2); A2 = ffma2(w1[q+1], u2.y, A2);
                    A3 = ffma2(w1[q], u3.x, A3); A3 = ffma2(w1[q+1], u3.y, A3);
                    C0 = ffma2(w2[q], u0.x, C0); C0 = ffma2(w2[q+1], u0.y, C0);
                    C1 = ffma2(w2[q], u1.x, C1); C1 = ffma2(w2[q+1], u1.y, C1);
                    C2 = ffma2(w2[q], u2.x, C2); C2 = ffma2(w2[q+1], u2.y, C2);
                    C3 = ffma2(w2[q], u3.x, C3); C3 = ffma2(w2[q+1], u3.y, C3);
                }
                const float4 xv = *(const float4*)&xsh[t][cb];
                float lo, hi;
                upk2(A0, lo, hi); const float g10 = (lo + hi) + fmaf(xv.x, wih1, bias1);
                upk2(A1, lo, hi); const float g11 = (lo + hi) + fmaf(xv.y, wih1, bias1);
                upk2(A2, lo, hi); const float g12 = (lo + hi) + fmaf(xv.z, wih1, bias1);
                upk2(A3, lo, hi); const float g13 = (lo + hi) + fmaf(xv.w, wih1, bias1);
                upk2(C0, lo, hi); const float g20 = (lo + hi) + fmaf(xv.x, wih2, bias2);
                upk2(C1, lo, hi); const float g21 = (lo + hi) + fmaf(xv.y, wih2, bias2);
                upk2(C2, lo, hi); const float g22 = (lo + hi) + fmaf(xv.z, wih2, bias2);
                upk2(C3, lo, hi); const float g23 = (lo + hi) + fmaf(xv.w, wih2, bias2);

                // activations (sigmoid via tanh identity; g row raw tanh)
                const float s10 = fmaf(0.5f, tanha(0.5f * g10), 0.5f);
                const float s11 = fmaf(0.5f, tanha(0.5f * g11), 0.5f);
                const float s12 = fmaf(0.5f, tanha(0.5f * g12), 0.5f);
                const float s13 = fmaf(0.5f, tanha(0.5f * g13), 0.5f);
                const float s20 = fmaf(m2, tanha(sc2 * g20), a2c);
                const float s21 = fmaf(m2, tanha(sc2 * g21), a2c);
                const float s22 = fmaf(m2, tanha(sc2 * g22), a2c);
                const float s23 = fmaf(m2, tanha(sc2 * g23), a2c);

                u64 a1p0 = pk2(s10, s11), a1p1 = pk2(s12, s13);
                u64 a2p0 = pk2(s20, s21), a2p1 = pk2(s22, s23);

                // p0: sig(i)*tanh(g) -> partner
                u64 pr0 = fmul2(a1p0, a2p0);
                u64 pr1 = fmul2(a1p1, a2p1);
                u64 rr0 = __shfl_xor_sync(wmask, pr0, 1, 32);
                u64 rr1 = __shfl_xor_sync(wmask, pr1, 1, 32);

                if (p == 1) {
                    // c = sig(f)*c + sig(i)*tanh(g); h = sig(o)*tanh(c)
                    cst[ch * 2]     = ffma2(a1p0, cst[ch * 2],     rr0);
                    cst[ch * 2 + 1] = ffma2(a1p1, cst[ch * 2 + 1], rr1);
                    float c0, c1, c2, c3;
                    upk2(cst[ch * 2],     c0, c1);
                    upk2(cst[ch * 2 + 1], c2, c3);
                    const float h0v = s20 * tanha(c0);
                    const float h1v = s21 * tanha(c1);
                    const float h2v = s22 * tanha(c2);
                    const float h3v = s23 * tanha(c3);
                    const int jh = j >> 1, jl = j & 1;
                    ((float*)(hw + (cb + 0) * KP + jh))[jl] = h0v;
                    ((float*)(hw + (cb + 1) * KP + jh))[jl] = h1v;
                    ((float*)(hw + (cb + 2) * KP + jh))[jl] = h2v;
                    ((float*)(hw + (cb + 3) * KP + jh))[jl] = h3v;
                }
            }
        }
        __syncthreads();
    }

    // final FC for t = SEQLEN-1
    if (fcRole) {
        const u64* __restrict__ hv = &hsh[SEQLEN & 1][fb][0];
        u64 s0 = 0ull, s1 = 0ull;
        #pragma unroll
        for (int q = 0; q < KP; q += 2) {
            s0 = ffma2(hv[q],     wfc2[q],     s0);
            s1 = ffma2(hv[q + 1], wfc2[q + 1], s1);
        }
        float aa, ab, ac, ad;
        upk2(s0, aa, ab); upk2(s1, ac, ad);
        out[(b0 + fb) * SEQLEN + (SEQLEN - 1)] = (aa + ab) + (ac + ad) + bfc;
    }
}

extern "C" void kernel_launch(void* const* d_in, const int* in_sizes, int n_in,
                              void* d_out, int out_size) {
    const float* input = (const float*)d_in[0];
    const float* W_ih  = (const float*)d_in[1];
    const float* W_hh  = (const float*)d_in[2];
    const float* b_ih  = (const float*)d_in[3];
    const float* b_hh  = (const float*)d_in[4];
    const float* W_fc  = (const float*)d_in[5];
    const float* b_fc  = (const float*)d_in[6];
    // d_in[7] = future (0) — ignored.
    float* out = (float*)d_out;

    lstm9_kernel<<<BATCH / BT, NTHR>>>(input, W_ih, W_hh, b_ih, b_hh,
                                       W_fc, b_fc, out);
}

// round 11
// speedup vs baseline: 1.4684x; 1.0748x over previous
#include <cuda_runtime.h>

// LSTM B=4096, T=999, I=1, H=51, O=1, future=0.
//
// R9 core (gate-pair threads, 104 weight regs, tanh.approx acts, one
// barrier/step, 3 CTAs/SM) rescheduled for a SINGLE WAVE:
//   BT=10, grid=410 <= 444 slots -> no serialized straggler wave (R9's
//   512-CTA grid left 68 CTAs running their full 999-step recurrence
//   after wave 1 -- the dominant waste).
// Last CTA clamps batch loads / guards stores (covers batches 4090..4095).
// Chunks 4+4+2 via CH-templated inlined lambda, compile-time indices only;
// memory clobber between chunks keeps regs under the 170 cap.

#define HID    51
#define KP     26
#define SEQLEN 999
#define BT     10
#define NTHR   128
#define BATCH  4096
#define GRID   410          // ceil(4096/10)

typedef unsigned long long u64;
template <int N> struct IC { static constexpr int v = N; };

__device__ __forceinline__ u64 pk2(float lo, float hi) {
    u64 r;
    asm("mov.b64 %0, {%1, %2};"
        : "=l"(r) : "r"(__float_as_uint(lo)), "r"(__float_as_uint(hi)));
    return r;
}
__device__ __forceinline__ void upk2(u64 v, float& lo, float& hi) {
    unsigned a, b;
    asm("mov.b64 {%0, %1}, %2;" : "=r"(a), "=r"(b) : "l"(v));
    lo = __uint_as_float(a); hi = __uint_as_float(b);
}
__device__ __forceinline__ u64 ffma2(u64 a, u64 b, u64 c) {
    u64 d; asm("fma.rn.f32x2 %0, %1, %2, %3;" : "=l"(d) : "l"(a), "l"(b), "l"(c));
    return d;
}
__device__ __forceinline__ u64 fmul2(u64 a, u64 b) {
    u64 d; asm("mul.rn.f32x2 %0, %1, %2;" : "=l"(d) : "l"(a), "l"(b));
    return d;
}
__device__ __forceinline__ float tanha(float x) {
    float r; asm("tanh.approx.f32 %0, %1;" : "=f"(r) : "f"(x));
    return r;
}

__global__ __launch_bounds__(NTHR, 3)
void lstm10_kernel(const float* __restrict__ input,   // (B, T, 1)
                   const float* __restrict__ W_ih,    // (4H, 1)
                   const float* __restrict__ W_hh,    // (4H, H)
                   const float* __restrict__ b_ih,    // (4H)
                   const float* __restrict__ b_hh,    // (4H)
                   const float* __restrict__ W_fc,    // (1, H)
                   const float* __restrict__ b_fc,    // (1)
                   float* __restrict__ out)           // (B, T, 1)
{
    __shared__ __align__(16) float xsh[SEQLEN][BT];   // 39.96 KB
    __shared__ __align__(16) u64   hsh[2][BT][KP];    // 4.16 KB, batch-major
    __shared__ __align__(16) u64   wfc2[KP];

    const int tid = threadIdx.x;
    const int b0  = blockIdx.x * BT;

    // ---- one-time init (batch-clamped for the last CTA) ----
    #pragma unroll
    for (int b = 0; b < BT; b++) {
        const int bidx = min(b0 + b, BATCH - 1);
        for (int idx = tid; idx < SEQLEN; idx += NTHR)
            xsh[idx][b] = input[bidx * SEQLEN + idx];
    }
    for (int idx = tid; idx < 2 * BT * KP; idx += NTHR)
        ((u64*)hsh)[idx] = 0ull;                      // h0 = 0 (+ pad lanes)
    if (tid < KP)
        wfc2[tid] = pk2(W_fc[2 * tid],
                        (2 * tid + 1 < HID) ? W_fc[2 * tid + 1] : 0.0f);

    const int j = tid >> 1;           // unit 0..50 (active)
    const int p = tid & 1;            // 0 = (i,g), 1 = (f,o)+cell
    const bool active = (tid < 2 * HID);              // < 102
    const bool fcRole = (tid >= 104 && tid < 104 + BT);
    const int  fb     = tid - 104;
    const unsigned wmask = (tid >= 96) ? 0x3Fu : 0xFFFFFFFFu;

    const int row1 = p * HID + j;         // i or f
    const int row2 = (2 + p) * HID + j;   // g or o

    u64 w1[KP], w2[KP];
    float bias1 = 0.f, bias2 = 0.f, wih1 = 0.f, wih2 = 0.f;
    if (active) {
        #pragma unroll
        for (int q = 0; q < KP; q++) {
            int k0 = 2 * q, k1 = 2 * q + 1;
            float a0 = W_hh[row1 * HID + k0];
            float a1 = (k1 < HID) ? W_hh[row1 * HID + k1] : 0.0f;
            float c0 = W_hh[row2 * HID + k0];
            float c1 = (k1 < HID) ? W_hh[row2 * HID + k1] : 0.0f;
            w1[q] = pk2(a0, a1);
            w2[q] = pk2(c0, c1);
        }
        bias1 = b_ih[row1] + b_hh[row1];
        bias2 = b_ih[row2] + b_hh[row2];
        wih1  = W_ih[row1];
        wih2  = W_ih[row2];
    } else {
        #pragma unroll
        for (int q = 0; q < KP; q++) { w1[q] = 0ull; w2[q] = 0ull; }
    }
    const float bfc = b_fc[0];

    // act = m2 * tanh(sc2 * a) + a2c  (row1 always sigmoid; row2: g->tanh,
    // o->sigmoid).  sigmoid(x) = 0.5*tanh(0.5x) + 0.5.
    const float sc2 = (p == 0) ? 1.0f : 0.5f;
    const float m2  = (p == 0) ? 1.0f : 0.5f;
    const float a2c = (p == 0) ? 0.0f : 0.5f;

    u64 cst0 = 0ull, cst1 = 0ull, cst2 = 0ull, cst3 = 0ull, cst4 = 0ull;

    __syncthreads();

    #pragma unroll 1
    for (int t = 0; t < SEQLEN; t++) {
        const u64* __restrict__ hb = &hsh[t & 1][0][0];
        u64* __restrict__ hw = &hsh[(t + 1) & 1][0][0];
        const float* __restrict__ xrow = &xsh[t][0];

        // ---- deferred FC for step t-1 (idle lanes; stable buffer) ----
        if (fcRole && t > 0) {
            const u64* __restrict__ hv = hb + fb * KP;
            u64 s0 = 0ull, s1 = 0ull;
            #pragma unroll
            for (int q = 0; q < KP; q += 2) {
                s0 = ffma2(hv[q],     wfc2[q],     s0);
                s1 = ffma2(hv[q + 1], wfc2[q + 1], s1);
            }
            float aa, ab, ac, ad;
            upk2(s0, aa, ab); upk2(s1, ac, ad);
            if (b0 + fb < BATCH)
                out[(b0 + fb) * SEQLEN + (t - 1)] = (aa + ab) + (ac + ad) + bfc;
        }

        if (active) {
            // CH-templated chunk: compile-time indices only.
            auto chunkf = [&](auto CHC, int cb, u64& cA, u64& cB) {
                constexpr int CH = CHC.v;
                u64 A[CH], C[CH];
                #pragma unroll
                for (int i = 0; i < CH; i++) { A[i] = 0ull; C[i] = 0ull; }
                #pragma unroll
                for (int q = 0; q < KP; q += 2) {
                    #pragma unroll
                    for (int i = 0; i < CH; i++) {
                        ulonglong2 u = *(const ulonglong2*)(hb + (cb + i) * KP + q);
                        A[i] = ffma2(w1[q], u.x, A[i]);
                        A[i] = ffma2(w1[q + 1], u.y, A[i]);
                        C[i] = ffma2(w2[q], u.x, C[i]);
                        C[i] = ffma2(w2[q + 1], u.y, C[i]);
                    }
                }
                float s1a[CH], s2a[CH];
                #pragma unroll
                for (int i = 0; i < CH; i += 2) {
                    // x rows are 40 B -> float2 (8-aligned at all offsets)
                    const float2 xv = *(const float2*)(xrow + cb + i);
                    float lo, hi;
                    upk2(A[i], lo, hi);
                    float g1 = (lo + hi) + fmaf(xv.x, wih1, bias1);
                    upk2(C[i], lo, hi);
                    float g2 = (lo + hi) + fmaf(xv.x, wih2, bias2);
                    s1a[i] = fmaf(0.5f, tanha(0.5f * g1), 0.5f);
                    s2a[i] = fmaf(m2, tanha(sc2 * g2), a2c);
                    upk2(A[i + 1], lo, hi);
                    g1 = (lo + hi) + fmaf(xv.y, wih1, bias1);
                    upk2(C[i + 1], lo, hi);
                    g2 = (lo + hi) + fmaf(xv.y, wih2, bias2);
                    s1a[i + 1] = fmaf(0.5f, tanha(0.5f * g1), 0.5f);
                    s2a[i + 1] = fmaf(m2, tanha(sc2 * g2), a2c);
                }
                #pragma unroll
                for (int pp = 0; pp < CH / 2; pp++) {
                    u64 a1p = pk2(s1a[2 * pp], s1a[2 * pp + 1]);
                    u64 a2p = pk2(s2a[2 * pp], s2a[2 * pp + 1]);
                    u64 pr = fmul2(a1p, a2p);          // p0: sig(i)*tanh(g)
                    u64 rr = __shfl_xor_sync(wmask, pr, 1, 32);
                    if (p == 1) {
                        u64& cc = (pp == 0) ? cA : cB;
                        cc = ffma2(a1p, cc, rr);
                        float c0f, c1f; upk2(cc, c0f, c1f);
                        const float h0v = s2a[2 * pp]     * tanha(c0f);
                        const float h1v = s2a[2 * pp + 1] * tanha(c1f);
                        const int jh = j >> 1, jl = j & 1;
                        ((float*)(hw + (cb + 2 * pp) * KP + jh))[jl]     = h0v;
                        ((float*)(hw + (cb + 2 * pp + 1) * KP + jh))[jl] = h1v;
                    }
                }
            };

            chunkf(IC<4>{}, 0, cst0, cst1);
            asm volatile("" ::: "memory");
            chunkf(IC<4>{}, 4, cst2, cst3);
            asm volatile("" ::: "memory");
            chunkf(IC<2>{}, 8, cst4, cst4);
        }
        __syncthreads();
    }

    // final FC for t = SEQLEN-1
    if (fcRole && b0 + fb < BATCH) {
        const u64* __restrict__ hv = &hsh[SEQLEN & 1][fb][0];
        u64 s0 = 0ull, s1 = 0ull;
        #pragma unroll
        for (int q = 0; q < KP; q += 2) {
            s0 = ffma2(hv[q],     wfc2[q],     s0);
            s1 = ffma2(hv[q + 1], wfc2[q + 1], s1);
        }
        float aa, ab, ac, ad;
        upk2(s0, aa, ab); upk2(s1, ac, ad);
        out[(b0 + fb) * SEQLEN + (SEQLEN - 1)] = (aa + ab) + (ac + ad) + bfc;
    }
}

extern "C" void kernel_launch(void* const* d_in, const int* in_sizes, int n_in,
                              void* d_out, int out_size) {
    const float* input = (const float*)d_in[0];
    const float* W_ih  = (const float*)d_in[1];
    const float* W_hh  = (const float*)d_in[2];
    const float* b_ih  = (const float*)d_in[3];
    const float* b_hh  = (const float*)d_in[4];
    const float* W_fc  = (const float*)d_in[5];
    const float* b_fc  = (const float*)d_in[6];
    // d_in[7] = future (0) — ignored.
    float* out = (float*)d_out;

    lstm10_kernel<<<GRID, NTHR>>>(input, W_ih, W_hh, b_ih, b_hh,
                                  W_fc, b_fc, out);
}